// round 7
// baseline (speedup 1.0000x reference)
#include <cuda_runtime.h>

#define NR    8192
#define NQ    4096
#define KNN_K 16
#define C4    64           // 256 channels / 4 (float4)

#define QPW             2                   // queries per warp
#define WARPS_PER_BLOCK 14
#define KNN_THREADS     (WARPS_PER_BLOCK * 32)   // 448
#define WARP_PAIRS      (NQ / QPW)               // 2048
#define KNN_BLOCKS      ((WARP_PAIRS + WARPS_PER_BLOCK - 1) / WARPS_PER_BLOCK) // 147
#define SAMPLE_ITERS    64         // phase-1 samples 32*64 = 2048 refs
#define FULL_ITERS      (NR / 32)  // 256
#define BUF_CAP         256

typedef unsigned long long ull;

__device__ int g_knn_idx[NQ * KNN_K];

// q2/r2: jnp.sum(x*x) = sequential add of rn squares (no FMA).
__device__ __forceinline__ float sq3(float x, float y, float z) {
    return __fadd_rn(__fadd_rn(__fmul_rn(x, x), __fmul_rn(y, y)), __fmul_rn(z, z));
}
// cross: XLA dot accumulation = fmuladd chain (seed = rn product).
__device__ __forceinline__ float dot3_fma(float ax, float ay, float az,
                                          float bx, float by, float bz) {
    return __fmaf_rn(az, bz, __fmaf_rn(ay, by, __fmul_rn(ax, bx)));
}
// Lexicographic (dist, idx) as one sortable u64 (buffer / final sort only).
__device__ __forceinline__ ull make_key(float d, int r) {
    unsigned b = __float_as_uint(d);
    b ^= ((unsigned)((int)b >> 31)) | 0x80000000u;
    return ((ull)b << 32) | (unsigned)r;
}
__device__ __forceinline__ bool pair_less(float d1, int i1, float d2, int i2) {
    return (d1 < d2) || (d1 == d2 && i1 < i2);
}

// Bitonic-sort 32 (d,idx) lane minima ascending; return 16th smallest dist.
__device__ __forceinline__ float warp_tau(float bd, int br, int lane) {
    float sd = bd; int si = br;
#pragma unroll
    for (int kk = 2; kk <= 32; kk <<= 1) {
#pragma unroll
        for (int j = kk >> 1; j > 0; j >>= 1) {
            float od = __shfl_xor_sync(0xffffffffu, sd, j);
            int   oi = __shfl_xor_sync(0xffffffffu, si, j);
            bool keepMin = (((lane & j) == 0) == ((lane & kk) == 0));
            bool oless = pair_less(od, oi, sd, si);
            if (oless == keepMin) { sd = od; si = oi; }
        }
    }
    return __shfl_sync(0xffffffffu, sd, KNN_K - 1);
}

// Extract the 16 smallest keys from wbuf[0..cnt) into g_knn_idx for query q.
__device__ __forceinline__ void select16(ull* wbuf, int cnt, int q, int lane) {
    for (int sel = 0; sel < KNN_K; ++sel) {
        ull best = ~0ull;
        int bpos = -1;
        for (int i = lane; i < cnt; i += 32) {
            ull v = wbuf[i];
            if (v < best) { best = v; bpos = i; }
        }
#pragma unroll
        for (int off = 16; off > 0; off >>= 1) {
            ull ob = __shfl_down_sync(0xffffffffu, best, off);
            int op = __shfl_down_sync(0xffffffffu, bpos, off);
            if (ob < best) { best = ob; bpos = op; }
        }
        bpos = __shfl_sync(0xffffffffu, bpos, 0);
        if (lane == 0) g_knn_idx[q * KNN_K + sel] = (int)(wbuf[bpos] & 0xffffffffu);
        if (lane == (bpos & 31)) wbuf[bpos] = ~0ull;
        __syncwarp();
    }
}

// One warp per TWO queries: each SMEM ref load (x,y,z,r2) feeds both queries'
// distance FMAs, halving LDS bytes per query. Two-pass threshold selection.
__global__ void __launch_bounds__(KNN_THREADS, 1) knn_kernel(
        const float* __restrict__ xyz_prev,
        const float* __restrict__ xyz_cur) {
    extern __shared__ unsigned char smraw[];
    float4* sref = (float4*)smraw;                          // 128 KB
    ull*    bufs = (ull*)(smraw + NR * sizeof(float4));     // 14*2*256*8 = 56 KB

    const int tid = threadIdx.x;
    // fused pack: read xyz triples, compute r2, stage as float4
    for (int i = tid; i < NR; i += KNN_THREADS) {
        float x = xyz_prev[3 * i + 0];
        float y = xyz_prev[3 * i + 1];
        float z = xyz_prev[3 * i + 2];
        sref[i] = make_float4(x, y, z, sq3(x, y, z));
    }
    __syncthreads();

    const int warp = tid >> 5;
    const int lane = tid & 31;
    const int q0 = (blockIdx.x * WARPS_PER_BLOCK + warp) * QPW;
    if (q0 >= NQ) return;                    // whole warp exits together
    const int q1 = q0 + 1;
    ull* wbuf0 = bufs + warp * (QPW * BUF_CAP);
    ull* wbuf1 = wbuf0 + BUF_CAP;

    const float ax = xyz_cur[3 * q0 + 0], ay = xyz_cur[3 * q0 + 1], az = xyz_cur[3 * q0 + 2];
    const float bx = xyz_cur[3 * q1 + 0], by = xyz_cur[3 * q1 + 1], bz = xyz_cur[3 * q1 + 2];
    const float a2 = sq3(ax, ay, az);
    const float b2 = sq3(bx, by, bz);

    // ---- Phase 1: per-lane min over 2048 sampled refs (2 accs x 2 queries) ----
    const float INF = __int_as_float(0x7f800000);
    float a_d0 = INF, a_d1 = INF, b_d0 = INF, b_d1 = INF;
    int   a_r0 = 0x7fffffff, a_r1 = a_r0, b_r0 = a_r0, b_r1 = a_r0;
#pragma unroll 2
    for (int i = 0; i < SAMPLE_ITERS; i += 2) {
#pragma unroll
        for (int j = 0; j < 2; ++j) {
            const int r = lane + 32 * (i + j);
            const float4 p = sref[r];
            const float ca = dot3_fma(ax, ay, az, p.x, p.y, p.z);
            const float cb = dot3_fma(bx, by, bz, p.x, p.y, p.z);
            const float da = __fmaf_rn(-2.0f, ca, __fadd_rn(a2, p.w));
            const float db = __fmaf_rn(-2.0f, cb, __fadd_rn(b2, p.w));
            if (j == 0) {
                if (da < a_d0) { a_d0 = da; a_r0 = r; }
                if (db < b_d0) { b_d0 = db; b_r0 = r; }
            } else {
                if (da < a_d1) { a_d1 = da; a_r1 = r; }
                if (db < b_d1) { b_d1 = db; b_r1 = r; }
            }
        }
    }
    // lexicographic combine of the two accumulators per query
    float a_bd = a_d0; int a_br = a_r0;
    if (pair_less(a_d1, a_r1, a_bd, a_br)) { a_bd = a_d1; a_br = a_r1; }
    float b_bd = b_d0; int b_br = b_r0;
    if (pair_less(b_d1, b_r1, b_bd, b_br)) { b_bd = b_d1; b_br = b_r1; }

    const float tau_a = warp_tau(a_bd, a_br, lane);
    const float tau_b = warp_tau(b_bd, b_br, lane);

    // ---- Phase 2: full scan; one ref load serves both queries ----
    int base_a = 0, base_b = 0;
    const unsigned lt_mask = (1u << lane) - 1u;
#pragma unroll 2
    for (int i = 0; i < FULL_ITERS; ++i) {
        const int r = lane + 32 * i;
        const float4 p = sref[r];
        const float ca = dot3_fma(ax, ay, az, p.x, p.y, p.z);
        const float cb = dot3_fma(bx, by, bz, p.x, p.y, p.z);
        const float da = __fmaf_rn(-2.0f, ca, __fadd_rn(a2, p.w));
        const float db = __fmaf_rn(-2.0f, cb, __fadd_rn(b2, p.w));

        const bool pa = (da <= tau_a);
        const unsigned ma = __ballot_sync(0xffffffffu, pa);
        if (pa) {
            int pos = base_a + __popc(ma & lt_mask);
            if (pos < BUF_CAP) wbuf0[pos] = make_key(da, r);
        }
        base_a += __popc(ma);

        const bool pb = (db <= tau_b);
        const unsigned mb = __ballot_sync(0xffffffffu, pb);
        if (pb) {
            int pos = base_b + __popc(mb & lt_mask);
            if (pos < BUF_CAP) wbuf1[pos] = make_key(db, r);
        }
        base_b += __popc(mb);
    }
    __syncwarp();

    // ---- Phase 3: 16 argmin-extract rounds per query ----
    select16(wbuf0, (base_a < BUF_CAP) ? base_a : BUF_CAP, q0, lane);
    select16(wbuf1, (base_b < BUF_CAP) ? base_b : BUF_CAP, q1, lane);
}

// One block per query. blockDim = (64, 4). cur features in registers, reused
// across 4 neighbors. Output row (q*16+j): [prev[idx]-cur | cur], 512 f32.
__global__ void __launch_bounds__(256) gather_kernel(
        const float4* __restrict__ feat_prev,
        const float4* __restrict__ feat_cur,
        float4* __restrict__ out) {
    const int q  = blockIdx.x;
    const int c4 = threadIdx.x;   // 0..63
    const int y  = threadIdx.y;   // 0..3

    const float4 cur = feat_cur[q * C4 + c4];

#pragma unroll
    for (int jj = 0; jj < 4; ++jj) {
        const int j = jj * 4 + y;
        const int idx = __ldg(&g_knn_idx[q * KNN_K + j]);
        const float4 p = feat_prev[idx * C4 + c4];
        float4 dv;
        dv.x = p.x - cur.x; dv.y = p.y - cur.y;
        dv.z = p.z - cur.z; dv.w = p.w - cur.w;
        const int row = q * KNN_K + j;          // 0..65535
        __stcs(&out[row * 128 + c4], dv);
        __stcs(&out[row * 128 + C4 + c4], cur);
    }
}

extern "C" void kernel_launch(void* const* d_in, const int* in_sizes, int n_in,
                              void* d_out, int out_size) {
    const float*  xyz_prev  = (const float*)d_in[0];
    const float*  xyz_cur   = (const float*)d_in[1];
    const float4* feat_prev = (const float4*)d_in[2];
    const float4* feat_cur  = (const float4*)d_in[3];
    float4* out = (float4*)d_out;

    (void)in_sizes; (void)n_in; (void)out_size;

    const int smem = NR * sizeof(float4) + WARPS_PER_BLOCK * QPW * BUF_CAP * sizeof(ull);
    cudaFuncSetAttribute(knn_kernel, cudaFuncAttributeMaxDynamicSharedMemorySize, smem);

    knn_kernel<<<KNN_BLOCKS, KNN_THREADS, smem>>>(xyz_prev, xyz_cur);
    gather_kernel<<<NQ, dim3(64, 4)>>>(feat_prev, feat_cur, out);
}

// round 8
// speedup vs baseline: 1.2458x; 1.2458x over previous
#include <cuda_runtime.h>

#define NR    8192
#define NQ    4096
#define KNN_K 16
#define C4    64           // 256 channels / 4 (float4)

#define WARPS_PER_BLOCK 28
#define KNN_THREADS     (WARPS_PER_BLOCK * 32)          // 896
#define KNN_BLOCKS      ((NQ + WARPS_PER_BLOCK - 1) / WARPS_PER_BLOCK)  // 147
#define SAMPLE_ITERS    64         // phase-1 samples 32*64 = 2048 refs
#define FULL_ITERS      (NR / 32)  // 256
#define BUF_CAP         256
#define TAU_SLACK       1e-3f      // >> max |d - (q2 + t)| rounding error (~2e-5)

typedef unsigned long long ull;

__device__ int g_knn_idx[NQ * KNN_K];

// q2/r2: jnp.sum(x*x) = sequential add of rn squares (no FMA).
__device__ __forceinline__ float sq3(float x, float y, float z) {
    return __fadd_rn(__fadd_rn(__fmul_rn(x, x), __fmul_rn(y, y)), __fmul_rn(z, z));
}
// cross: XLA dot accumulation = fmuladd chain (seed = rn product).
__device__ __forceinline__ float dot3_fma(float ax, float ay, float az,
                                          float bx, float by, float bz) {
    return __fmaf_rn(az, bz, __fmaf_rn(ay, by, __fmul_rn(ax, bx)));
}
// Lexicographic (dist, idx) as one sortable u64 (survivor buffer only).
__device__ __forceinline__ ull make_key(float d, int r) {
    unsigned b = __float_as_uint(d);
    b ^= ((unsigned)((int)b >> 31)) | 0x80000000u;
    return ((ull)b << 32) | (unsigned)r;
}

// One warp per query. Refs (x,y,z,r2) staged in SMEM. Two-pass threshold
// selection, index-free phase 1 on shifted distances t = d - q2.
__global__ void __launch_bounds__(KNN_THREADS, 1) knn_kernel(
        const float* __restrict__ xyz_prev,
        const float* __restrict__ xyz_cur) {
    extern __shared__ unsigned char smraw[];
    float4* sref = (float4*)smraw;                          // 128 KB
    ull*    bufs = (ull*)(smraw + NR * sizeof(float4));     // 28*256*8 = 56 KB

    const int tid = threadIdx.x;
    // fused pack: read xyz triples, compute r2, stage as float4
    for (int i = tid; i < NR; i += KNN_THREADS) {
        float x = xyz_prev[3 * i + 0];
        float y = xyz_prev[3 * i + 1];
        float z = xyz_prev[3 * i + 2];
        sref[i] = make_float4(x, y, z, sq3(x, y, z));
    }
    __syncthreads();

    const int warp = tid >> 5;
    const int lane = tid & 31;
    const int q = blockIdx.x * WARPS_PER_BLOCK + warp;
    if (q >= NQ) return;                    // whole warp exits together
    ull* wbuf = bufs + warp * BUF_CAP;

    const float qx = xyz_cur[3 * q + 0];
    const float qy = xyz_cur[3 * q + 1];
    const float qz = xyz_cur[3 * q + 2];
    const float q2 = sq3(qx, qy, qz);

    // ---- Phase 1: per-lane min of t = r2 - 2*cross over 2048 sampled refs ----
    const float INF = __int_as_float(0x7f800000);
    float m0 = INF, m1 = INF, m2 = INF, m3 = INF;
    for (int i = 0; i < SAMPLE_ITERS; i += 4) {
        const float4 p0 = sref[lane + 32 * (i + 0)];
        const float4 p1 = sref[lane + 32 * (i + 1)];
        const float4 p2 = sref[lane + 32 * (i + 2)];
        const float4 p3 = sref[lane + 32 * (i + 3)];
        const float t0 = __fmaf_rn(-2.0f, dot3_fma(qx, qy, qz, p0.x, p0.y, p0.z), p0.w);
        const float t1 = __fmaf_rn(-2.0f, dot3_fma(qx, qy, qz, p1.x, p1.y, p1.z), p1.w);
        const float t2 = __fmaf_rn(-2.0f, dot3_fma(qx, qy, qz, p2.x, p2.y, p2.z), p2.w);
        const float t3 = __fmaf_rn(-2.0f, dot3_fma(qx, qy, qz, p3.x, p3.y, p3.z), p3.w);
        m0 = fminf(m0, t0);
        m1 = fminf(m1, t1);
        m2 = fminf(m2, t2);
        m3 = fminf(m3, t3);
    }
    float sd = fminf(fminf(m0, m1), fminf(m2, m3));

    // float-only bitonic sort of the 32 lane minima; tau = 16th smallest + slack
#pragma unroll
    for (int kk = 2; kk <= 32; kk <<= 1) {
#pragma unroll
        for (int j = kk >> 1; j > 0; j >>= 1) {
            const float o = __shfl_xor_sync(0xffffffffu, sd, j);
            const bool keepMin = (((lane & j) == 0) == ((lane & kk) == 0));
            sd = keepMin ? fminf(sd, o) : fmaxf(sd, o);
        }
    }
    const float tauq = __shfl_sync(0xffffffffu, sd, KNN_K - 1) + TAU_SLACK;
    // any ref with exact d <= true d16 has t <= t16_sampled + 2*rnd_err < tauq

    // ---- Phase 2: full scan; survivors = { t <= tauq } (superset of top-16) ----
    int base = 0;
    const unsigned lt_mask = (1u << lane) - 1u;
    for (int i = 0; i < FULL_ITERS; i += 4) {
        const float4 p0 = sref[lane + 32 * (i + 0)];
        const float4 p1 = sref[lane + 32 * (i + 1)];
        const float4 p2 = sref[lane + 32 * (i + 2)];
        const float4 p3 = sref[lane + 32 * (i + 3)];
        const float c0 = dot3_fma(qx, qy, qz, p0.x, p0.y, p0.z);
        const float c1 = dot3_fma(qx, qy, qz, p1.x, p1.y, p1.z);
        const float c2 = dot3_fma(qx, qy, qz, p2.x, p2.y, p2.z);
        const float c3 = dot3_fma(qx, qy, qz, p3.x, p3.y, p3.z);
        const float t0 = __fmaf_rn(-2.0f, c0, p0.w);
        const float t1 = __fmaf_rn(-2.0f, c1, p1.w);
        const float t2 = __fmaf_rn(-2.0f, c2, p2.w);
        const float t3 = __fmaf_rn(-2.0f, c3, p3.w);

#pragma unroll
        for (int j = 0; j < 4; ++j) {
            const float t  = (j == 0) ? t0 : (j == 1) ? t1 : (j == 2) ? t2 : t3;
            const float pw = (j == 0) ? p0.w : (j == 1) ? p1.w : (j == 2) ? p2.w : p3.w;
            const float cr = (j == 0) ? c0 : (j == 1) ? c1 : (j == 2) ? c2 : c3;
            const bool pred = (t <= tauq);
            const unsigned m = __ballot_sync(0xffffffffu, pred);
            if (pred) {
                // exact reference-rounded distance, only on the rare path
                const float d = __fmaf_rn(-2.0f, cr, __fadd_rn(q2, pw));
                const int pos = base + __popc(m & lt_mask);
                if (pos < BUF_CAP) wbuf[pos] = make_key(d, lane + 32 * (i + j));
            }
            base += __popc(m);
        }
    }
    const int cnt = (base < BUF_CAP) ? base : BUF_CAP;   // >= 16 guaranteed
    __syncwarp();

    // ---- Phase 3: 16 argmin-extract rounds over the small buffer ----
    for (int sel = 0; sel < KNN_K; ++sel) {
        ull best = ~0ull;
        int bpos = -1;
        for (int i = lane; i < cnt; i += 32) {
            const ull v = wbuf[i];
            if (v < best) { best = v; bpos = i; }
        }
#pragma unroll
        for (int off = 16; off > 0; off >>= 1) {
            const ull ob = __shfl_down_sync(0xffffffffu, best, off);
            const int op = __shfl_down_sync(0xffffffffu, bpos, off);
            if (ob < best) { best = ob; bpos = op; }
        }
        bpos = __shfl_sync(0xffffffffu, bpos, 0);
        if (lane == 0) g_knn_idx[q * KNN_K + sel] = (int)(wbuf[bpos] & 0xffffffffu);
        if (lane == (bpos & 31)) wbuf[bpos] = ~0ull;
        __syncwarp();
    }
}

// One block per query. blockDim = (64, 4). Thread y owns neighbors 4y..4y+3:
// one int4 idx load -> 4 independent gathers (MLP=4), cur reused from regs.
__global__ void __launch_bounds__(256) gather_kernel(
        const float4* __restrict__ feat_prev,
        const float4* __restrict__ feat_cur,
        float4* __restrict__ out) {
    const int q  = blockIdx.x;
    const int c4 = threadIdx.x;   // 0..63
    const int y  = threadIdx.y;   // 0..3

    const float4 cur = feat_cur[q * C4 + c4];
    const int4 iv = __ldg((const int4*)(g_knn_idx + q * KNN_K + 4 * y));

    const float4 p0 = feat_prev[iv.x * C4 + c4];
    const float4 p1 = feat_prev[iv.y * C4 + c4];
    const float4 p2 = feat_prev[iv.z * C4 + c4];
    const float4 p3 = feat_prev[iv.w * C4 + c4];

    const int row0 = q * KNN_K + 4 * y;
#pragma unroll
    for (int jj = 0; jj < 4; ++jj) {
        const float4 p = (jj == 0) ? p0 : (jj == 1) ? p1 : (jj == 2) ? p2 : p3;
        float4 dv;
        dv.x = p.x - cur.x; dv.y = p.y - cur.y;
        dv.z = p.z - cur.z; dv.w = p.w - cur.w;
        const long long row = row0 + jj;
        __stcs(&out[row * 128 + c4], dv);
        __stcs(&out[row * 128 + C4 + c4], cur);
    }
}

extern "C" void kernel_launch(void* const* d_in, const int* in_sizes, int n_in,
                              void* d_out, int out_size) {
    const float*  xyz_prev  = (const float*)d_in[0];
    const float*  xyz_cur   = (const float*)d_in[1];
    const float4* feat_prev = (const float4*)d_in[2];
    const float4* feat_cur  = (const float4*)d_in[3];
    float4* out = (float4*)d_out;

    (void)in_sizes; (void)n_in; (void)out_size;

    const int smem = NR * sizeof(float4) + WARPS_PER_BLOCK * BUF_CAP * sizeof(ull);
    cudaFuncSetAttribute(knn_kernel, cudaFuncAttributeMaxDynamicSharedMemorySize, smem);

    knn_kernel<<<KNN_BLOCKS, KNN_THREADS, smem>>>(xyz_prev, xyz_cur);
    gather_kernel<<<NQ, dim3(64, 4)>>>(feat_prev, feat_cur, out);
}